// round 4
// baseline (speedup 1.0000x reference)
#include <cuda_runtime.h>
#include <math.h>

// Problem dims
#define Bv 4096
#define Tt 28
#define In 28
#define Hh 512
#define Gg 1536   // 3*H
#define H2 1024   // 2*H

// ---------------- scratch (static device allocations; allowed) ----------------
__device__ float g_gxA[176160768];   // B*T*3H : gx layer0 fwd, later reused as gx layer1 fwd
__device__ float g_gxB[176160768];   // B*T*3H : gx layer0 bwd
__device__ float g_y0[117440512];    // B*T*2H : layer0 output
__device__ float g_gh[2 * 6291456];  // 2 * B*3H : per-step hidden-projection
__device__ float g_h[2 * 2097152];   // 2 * B*H  : layer0 fwd/bwd hidden state
__device__ float g_h1[2097152];      // B*H      : layer1 fwd hidden
__device__ float g_h1b[2097152];     // B*H      : layer1 bwd hidden (one step only)
__device__ float g_gx1b[6291456];    // B*3H     : layer1 bwd gx at t = T-1 only
__device__ float g_last[4194304];    // B*2H     : concat(h1f, h1b)
__device__ float g_z1[1048576];      // B*256    : fc1 output

// ---------------- generic tiled SGEMM: C = A @ W^T + bias ----------------
// A: (M,K) row-major with leading dim lda. W: (N,K) row-major (ld = K).
// C: (M,N) row-major with leading dim ldc. M,N must be multiples of 128.
// blockIdx.z selects op0/op1 (lets fwd+bwd recurrent GEMMs share one launch).
struct GemmOp {
    const float* A;
    const float* W;
    const float* bias;
    float* C;
};

__global__ void __launch_bounds__(256) sgemm_bias(GemmOp op0, GemmOp op1,
                                                  int lda, int ldc,
                                                  int M, int N, int K)
{
    GemmOp op = (blockIdx.z == 0) ? op0 : op1;

    __shared__ float As[8][128];
    __shared__ float Ws[8][128];

    const int tid  = threadIdx.x;
    const int bm   = blockIdx.y * 128;
    const int bn   = blockIdx.x * 128;
    const int lrow = tid >> 1;          // 0..127
    const int lcol = (tid & 1) * 4;     // 0 or 4
    const int tx   = tid & 15;
    const int ty   = tid >> 4;

    float acc[8][8];
#pragma unroll
    for (int i = 0; i < 8; i++)
#pragma unroll
        for (int j = 0; j < 8; j++) acc[i][j] = 0.f;

    const float* Ap = op.A + (size_t)(bm + lrow) * lda;
    const float* Wp = op.W + (size_t)(bn + lrow) * K;

    for (int k0 = 0; k0 < K; k0 += 8) {
        const int kc = k0 + lcol;
        float4 av, wv;
        if (kc + 3 < K) {
            av = *(const float4*)(Ap + kc);
            wv = *(const float4*)(Wp + kc);
        } else {
            av.x = (kc + 0 < K) ? Ap[kc + 0] : 0.f;
            av.y = (kc + 1 < K) ? Ap[kc + 1] : 0.f;
            av.z = (kc + 2 < K) ? Ap[kc + 2] : 0.f;
            av.w = (kc + 3 < K) ? Ap[kc + 3] : 0.f;
            wv.x = (kc + 0 < K) ? Wp[kc + 0] : 0.f;
            wv.y = (kc + 1 < K) ? Wp[kc + 1] : 0.f;
            wv.z = (kc + 2 < K) ? Wp[kc + 2] : 0.f;
            wv.w = (kc + 3 < K) ? Wp[kc + 3] : 0.f;
        }
        As[lcol + 0][lrow] = av.x;
        As[lcol + 1][lrow] = av.y;
        As[lcol + 2][lrow] = av.z;
        As[lcol + 3][lrow] = av.w;
        Ws[lcol + 0][lrow] = wv.x;
        Ws[lcol + 1][lrow] = wv.y;
        Ws[lcol + 2][lrow] = wv.z;
        Ws[lcol + 3][lrow] = wv.w;
        __syncthreads();

#pragma unroll
        for (int k = 0; k < 8; k++) {
            float ar[8], wr[8];
            *(float4*)&ar[0] = *(const float4*)&As[k][ty * 8];
            *(float4*)&ar[4] = *(const float4*)&As[k][ty * 8 + 4];
            *(float4*)&wr[0] = *(const float4*)&Ws[k][tx * 8];
            *(float4*)&wr[4] = *(const float4*)&Ws[k][tx * 8 + 4];
#pragma unroll
            for (int i = 0; i < 8; i++)
#pragma unroll
                for (int j = 0; j < 8; j++)
                    acc[i][j] = fmaf(ar[i], wr[j], acc[i][j]);
        }
        __syncthreads();
    }

#pragma unroll
    for (int i = 0; i < 8; i++) {
        float* Cp = op.C + (size_t)(bm + ty * 8 + i) * ldc + bn + tx * 8;
#pragma unroll
        for (int j = 0; j < 8; j += 4) {
            float4 v;
            v.x = acc[i][j + 0] + op.bias[bn + tx * 8 + j + 0];
            v.y = acc[i][j + 1] + op.bias[bn + tx * 8 + j + 1];
            v.z = acc[i][j + 2] + op.bias[bn + tx * 8 + j + 2];
            v.w = acc[i][j + 3] + op.bias[bn + tx * 8 + j + 3];
            *(float4*)(Cp + j) = v;
        }
    }
}

// ---------------- misc small kernels ----------------
__global__ void zero_kernel(float* p, int n)
{
    int i = blockIdx.x * blockDim.x + threadIdx.x;
    if (i < n) p[i] = 0.f;
}

__device__ __forceinline__ float sigmoidf_(float x)
{
    return 1.f / (1.f + expf(-x));
}

// Layer-0 gating: both directions (blockIdx.y = dir). Updates h in-place,
// writes y0 at the right time slot.
__global__ void gru_gate_l0(int s)
{
    const int idx = blockIdx.x * blockDim.x + threadIdx.x;  // over B*H
    const int dir = blockIdx.y;
    const int b = idx >> 9;       // /512
    const int j = idx & 511;
    const int t = (dir == 0) ? s : (Tt - 1 - s);

    const float* gx  = (dir == 0 ? g_gxA : g_gxB) + ((size_t)b * Tt + t) * Gg;
    const float* ghp = g_gh + ((size_t)dir * Bv + b) * Gg;
    float* hp = g_h + ((size_t)dir * Bv + b) * Hh + j;

    float r = sigmoidf_(gx[j] + ghp[j]);
    float z = sigmoidf_(gx[Hh + j] + ghp[Hh + j]);
    float n = tanhf(gx[2 * Hh + j] + r * ghp[2 * Hh + j]);
    float hv = *hp;
    float hn = (1.f - z) * n + z * hv;
    *hp = hn;
    g_y0[((size_t)b * Tt + t) * H2 + dir * Hh + j] = hn;
}

// Layer-1 forward gating (only the final hidden is needed; no y output).
__global__ void gru_gate_l1(int s)
{
    const int idx = blockIdx.x * blockDim.x + threadIdx.x;
    const int b = idx >> 9;
    const int j = idx & 511;

    const float* gx  = g_gxA + ((size_t)b * Tt + s) * Gg;
    const float* ghp = g_gh + (size_t)b * Gg;
    float* hp = g_h1 + (size_t)b * Hh + j;

    float r = sigmoidf_(gx[j] + ghp[j]);
    float z = sigmoidf_(gx[Hh + j] + ghp[Hh + j]);
    float n = tanhf(gx[2 * Hh + j] + r * ghp[2 * Hh + j]);
    float hv = *hp;
    *hp = (1.f - z) * n + z * hv;
}

// Layer-1 backward: output at original t=T-1 is the FIRST reversed-scan step,
// h0 = 0, so gh = b_hh and the result is (1-z)*n. One kernel, no GEMM.
__global__ void gate_l1b_last(const float* __restrict__ bhh)
{
    const int idx = blockIdx.x * blockDim.x + threadIdx.x;
    const int b = idx >> 9;
    const int j = idx & 511;

    const float* gx = g_gx1b + (size_t)b * Gg;
    float r = sigmoidf_(gx[j] + bhh[j]);
    float z = sigmoidf_(gx[Hh + j] + bhh[Hh + j]);
    float n = tanhf(gx[2 * Hh + j] + r * bhh[2 * Hh + j]);
    g_h1b[(size_t)b * Hh + j] = (1.f - z) * n;
}

__global__ void concat_last(void)
{
    const int idx = blockIdx.x * blockDim.x + threadIdx.x;  // B*2H
    const int b = idx >> 10;
    const int j = idx & 1023;
    float v = (j < Hh) ? g_h1[(size_t)b * Hh + j] : g_h1b[(size_t)b * Hh + (j - Hh)];
    g_last[(size_t)b * H2 + j] = v;
}

// BN + ReLU + fc2 + log_softmax. One block (256 threads) per batch row.
__global__ void head_kernel(const float* __restrict__ gamma, const float* __restrict__ beta,
                            const float* __restrict__ mean, const float* __restrict__ var,
                            const float* __restrict__ fc2w, const float* __restrict__ fc2b,
                            float* __restrict__ out)
{
    const int b = blockIdx.x;
    const int tid = threadIdx.x;
    __shared__ float a[256];
    __shared__ float logits[10];

    float v = g_z1[(size_t)b * 256 + tid];
    v = (v - mean[tid]) * rsqrtf(var[tid] + 1e-5f) * gamma[tid] + beta[tid];
    a[tid] = fmaxf(v, 0.f);
    __syncthreads();

    if (tid < 10) {
        float acc = fc2b[tid];
        const float* wrow = fc2w + tid * 256;
        for (int k = 0; k < 256; k++) acc = fmaf(a[k], wrow[k], acc);
        logits[tid] = acc;
    }
    __syncthreads();

    if (tid == 0) {
        float mx = logits[0];
        for (int i = 1; i < 10; i++) mx = fmaxf(mx, logits[i]);
        float s = 0.f;
        for (int i = 0; i < 10; i++) s += expf(logits[i] - mx);
        float lse = mx + logf(s);
        for (int i = 0; i < 10; i++) out[(size_t)b * 10 + i] = logits[i] - lse;
    }
}

// ---------------- host-side launch ----------------
extern "C" void kernel_launch(void* const* d_in, const int* in_sizes, int n_in,
                              void* d_out, int out_size)
{
    (void)in_sizes; (void)n_in;
    const float* x         = (const float*)d_in[0];
    const float* W_ih_l0   = (const float*)d_in[1];
    const float* W_hh_l0   = (const float*)d_in[2];
    const float* b_ih_l0   = (const float*)d_in[3];
    const float* b_hh_l0   = (const float*)d_in[4];
    const float* W_ih_l0r  = (const float*)d_in[5];
    const float* W_hh_l0r  = (const float*)d_in[6];
    const float* b_ih_l0r  = (const float*)d_in[7];
    const float* b_hh_l0r  = (const float*)d_in[8];
    const float* W_ih_l1   = (const float*)d_in[9];
    const float* W_hh_l1   = (const float*)d_in[10];
    const float* b_ih_l1   = (const float*)d_in[11];
    const float* b_hh_l1   = (const float*)d_in[12];
    const float* W_ih_l1r  = (const float*)d_in[13];
    const float* W_hh_l1r  = (const float*)d_in[14];
    const float* b_ih_l1r  = (const float*)d_in[15];
    const float* b_hh_l1r  = (const float*)d_in[16];
    const float* fc1_w     = (const float*)d_in[17];
    const float* fc1_b     = (const float*)d_in[18];
    const float* bn_gamma  = (const float*)d_in[19];
    const float* bn_beta   = (const float*)d_in[20];
    const float* bn_mean   = (const float*)d_in[21];
    const float* bn_var    = (const float*)d_in[22];
    const float* fc2_w     = (const float*)d_in[23];
    const float* fc2_b     = (const float*)d_in[24];
    float* out = (float*)d_out;
    (void)out_size;

    // Symbol addresses for scratch (query only — no allocation).
    float *p_gxA, *p_gxB, *p_y0, *p_gh, *p_h, *p_h1, *p_gx1b, *p_last, *p_z1;
    cudaGetSymbolAddress((void**)&p_gxA,  g_gxA);
    cudaGetSymbolAddress((void**)&p_gxB,  g_gxB);
    cudaGetSymbolAddress((void**)&p_y0,   g_y0);
    cudaGetSymbolAddress((void**)&p_gh,   g_gh);
    cudaGetSymbolAddress((void**)&p_h,    g_h);
    cudaGetSymbolAddress((void**)&p_h1,   g_h1);
    cudaGetSymbolAddress((void**)&p_gx1b, g_gx1b);
    cudaGetSymbolAddress((void**)&p_last, g_last);
    cudaGetSymbolAddress((void**)&p_z1,   g_z1);

    const int BH  = Bv * Hh;      // 2,097,152
    const int BG  = Bv * Gg;      // 6,291,456
    const int MT  = Bv * Tt;      // 114,688

    // 1) layer-0 input projections, fwd+bwd in one launch (z=2)
    {
        GemmOp f{ x, W_ih_l0,  b_ih_l0,  p_gxA };
        GemmOp r{ x, W_ih_l0r, b_ih_l0r, p_gxB };
        dim3 grid(Gg / 128, MT / 128, 2);
        sgemm_bias<<<grid, 256>>>(f, r, In, Gg, MT, Gg, In);
    }

    // 2) zero hidden states
    zero_kernel<<<(2 * BH + 255) / 256, 256>>>(p_h, 2 * BH);
    zero_kernel<<<(BH + 255) / 256, 256>>>(p_h1, BH);

    // 3) layer-0 recurrence: 28 steps, fwd+bwd fused per launch
    for (int s = 0; s < Tt; s++) {
        GemmOp f{ p_h,      W_hh_l0,  b_hh_l0,  p_gh };
        GemmOp r{ p_h + BH, W_hh_l0r, b_hh_l0r, p_gh + BG };
        dim3 grid(Gg / 128, Bv / 128, 2);
        sgemm_bias<<<grid, 256>>>(f, r, Hh, Gg, Bv, Gg, Hh);
        dim3 ggrid(BH / 256, 2);
        gru_gate_l0<<<ggrid, 256>>>(s);
    }

    // 4) layer-1 input projection (fwd, all t)  — reuses g_gxA
    {
        GemmOp f{ p_y0, W_ih_l1, b_ih_l1, p_gxA };
        dim3 grid(Gg / 128, MT / 128, 1);
        sgemm_bias<<<grid, 256>>>(f, f, H2, Gg, MT, Gg, H2);
    }

    // 5) layer-1 bwd input projection at t = T-1 only
    {
        GemmOp f{ p_y0 + (size_t)(Tt - 1) * H2, W_ih_l1r, b_ih_l1r, p_gx1b };
        dim3 grid(Gg / 128, Bv / 128, 1);
        sgemm_bias<<<grid, 256>>>(f, f, Tt * H2, Gg, Bv, Gg, H2);
    }

    // 6) layer-1 bwd: single gating step (h0 = 0)
    gate_l1b_last<<<BH / 256, 256>>>(b_hh_l1r);

    // 7) layer-1 fwd recurrence
    for (int s = 0; s < Tt; s++) {
        GemmOp f{ p_h1, W_hh_l1, b_hh_l1, p_gh };
        dim3 grid(Gg / 128, Bv / 128, 1);
        sgemm_bias<<<grid, 256>>>(f, f, Hh, Gg, Bv, Gg, Hh);
        gru_gate_l1<<<BH / 256, 256>>>(s);
    }

    // 8) head: concat -> fc1 -> bn/relu/fc2/log_softmax
    concat_last<<<(Bv * H2) / 256, 256>>>();
    {
        GemmOp f{ p_last, fc1_w, fc1_b, p_z1 };
        dim3 grid(256 / 128, Bv / 128, 1);
        sgemm_bias<<<grid, 256>>>(f, f, H2, 256, Bv, 256, H2);
    }
    head_kernel<<<Bv, 256>>>(bn_gamma, bn_beta, bn_mean, bn_var, fc2_w, fc2_b, out);
}

// round 6
// speedup vs baseline: 2.7833x; 2.7833x over previous
#include <cuda_runtime.h>
#include <cuda_bf16.h>
#include <math.h>
#include <stdint.h>

// Problem dims
#define Bv 4096
#define Tt 28
#define In 28
#define Hh 512
#define Gg 1536   // 3*H
#define H2 1024   // 2*H

// ---------------- scratch (static device allocations; allowed) ----------------
__device__ float g_gxA[176160768];   // B*T*3H : gx layer0 fwd, reused as gx layer1 fwd
__device__ float g_gxB[176160768];   // B*T*3H : gx layer0 bwd
__device__ float g_gh[2 * 6291456];  // 2 * B*3H : per-step hidden projection
__device__ float g_h[2 * 2097152];   // 2 * B*H  : layer0 fwd/bwd hidden (fp32 state)
__device__ float g_h1[2097152];      // B*H      : layer1 fwd hidden (fp32 state)
__device__ float g_h1b[2097152];     // B*H      : layer1 bwd hidden (one step)
__device__ float g_gx1b[6291456];    // B*3H     : layer1 bwd gx at t=T-1
__device__ float g_z1[1048576];      // B*256    : fc1 output

// Stacked-K bf16 operands: A' = [Ah|Ah|Al], W' = [Wh|Wl|Wh] so a single GEMM
// over K'=3K computes Ah*Wh + Ah*Wl + Al*Wh (fp32-grade accuracy).
__device__ __nv_bfloat16 g_xs[14680064];    // x stacked  [B*T, 128]  (Kp=32, 4 segs w/ zero pad)
__device__ __nv_bfloat16 g_ws[17694720];    // all weights stacked arena
__device__ __nv_bfloat16 g_y0s[352321536];  // y0 stacked [B*T, 3072]
__device__ __nv_bfloat16 g_hs[12582912];    // layer0 h stacked, 2 dirs x [B,1536]
__device__ __nv_bfloat16 g_h1s[6291456];    // layer1 h stacked [B,1536]
__device__ __nv_bfloat16 g_lasts[12582912]; // concat(h1f,h1b) stacked [B,3072]

// Weight arena offsets (bf16 elements)
#define WS_IH_L0   0          // 1536 x 128
#define WS_IH_L0R  196608
#define WS_HH_L0   393216     // 1536 x 1536
#define WS_HH_L0R  2752512
#define WS_HH_L1   5111808
#define WS_IH_L1   7471104    // 1536 x 3072
#define WS_IH_L1R  12189696
#define WS_FC1     16908288   // 256 x 3072

// ============================================================================
// PTX helpers (all baseline sm_80+ features; valid on .target sm_103)
// ============================================================================
__device__ __forceinline__ uint32_t smem_u32(const void* p) {
    uint32_t a;
    asm("{ .reg .u64 t; cvta.to.shared.u64 t, %1; cvt.u32.u64 %0, t; }" : "=r"(a) : "l"(p));
    return a;
}
__device__ __forceinline__ void cp16(uint32_t s, const void* g) {
    asm volatile("cp.async.cg.shared.global [%0], [%1], 16;" :: "r"(s), "l"(g));
}
__device__ __forceinline__ void ldsm4(uint32_t* r, uint32_t a) {
    asm volatile("ldmatrix.sync.aligned.m8n8.x4.shared.b16 {%0,%1,%2,%3}, [%4];"
                 : "=r"(r[0]), "=r"(r[1]), "=r"(r[2]), "=r"(r[3]) : "r"(a));
}
__device__ __forceinline__ void mma16816(float* d, const uint32_t* a, uint32_t b0, uint32_t b1) {
    asm volatile("mma.sync.aligned.m16n8k16.row.col.f32.bf16.bf16.f32 "
                 "{%0,%1,%2,%3}, {%4,%5,%6,%7}, {%8,%9}, {%0,%1,%2,%3};"
                 : "+f"(d[0]), "+f"(d[1]), "+f"(d[2]), "+f"(d[3])
                 : "r"(a[0]), "r"(a[1]), "r"(a[2]), "r"(a[3]), "r"(b0), "r"(b1));
}

// ============================================================================
// Pipelined bf16 GEMM: C = A @ W^T + bias (fp32 accum)
// A: [M,K'] bf16 ld=lda. W: [N,K'] bf16 ld=K'. C: fp32 [M,N] ld=ldc.
// M,N multiples of 128; K' multiple of 64. blockIdx.z selects op.
// 128x128x64 tiles, 3-stage cp.async, swizzled ldmatrix, 8 warps (64x32 each).
// ============================================================================
struct MOp {
    const __nv_bfloat16 *A, *W;
    const float *bias;
    float *C;
};

#define STAGE_B 32768               // A tile 16KB + W tile 16KB
#define SMEM_SZ (3 * STAGE_B)       // 98304

__device__ __forceinline__ void prefetch_stage(const MOp& op, uint32_t sb, int c,
                                               int bm, int bn, int lda, int K, int tid)
{
    const int st = c % 3;
    const uint32_t abase = sb + st * STAGE_B;
    const uint32_t wbase = abase + 16384;
    const int kc0 = c * 64;
#pragma unroll
    for (int i = 0; i < 4; i++) {
        int v = tid + i * 256;          // 0..1023
        int row = v >> 3, ch = v & 7;   // 128 rows x 8 chunks(16B)
        const __nv_bfloat16* g = op.A + (size_t)(bm + row) * lda + kc0 + ch * 8;
        cp16(abase + row * 128 + ((ch ^ (row & 7)) << 4), g);
    }
#pragma unroll
    for (int i = 0; i < 4; i++) {
        int v = tid + i * 256;
        int row = v >> 3, ch = v & 7;
        const __nv_bfloat16* g = op.W + (size_t)(bn + row) * K + kc0 + ch * 8;
        cp16(wbase + row * 128 + ((ch ^ (row & 7)) << 4), g);
    }
    asm volatile("cp.async.commit_group;");
}

__global__ void __launch_bounds__(256, 2) mma_gemm(MOp op0, MOp op1,
                                                   int lda, int ldc, int K)
{
    extern __shared__ char smem[];
    MOp op = (blockIdx.z == 0) ? op0 : op1;
    const uint32_t sb = smem_u32(smem);
    const int tid  = threadIdx.x;
    const int wid  = tid >> 5;
    const int lane = tid & 31;
    const int bm = blockIdx.y * 128;
    const int bn = blockIdx.x * 128;
    const int wm = (wid >> 2) * 64;   // 2 warp rows
    const int wn = (wid & 3) * 32;    // 4 warp cols

    float acc[4][4][4];
#pragma unroll
    for (int i = 0; i < 4; i++)
#pragma unroll
        for (int j = 0; j < 4; j++)
#pragma unroll
            for (int r = 0; r < 4; r++) acc[i][j][r] = 0.f;

    const int nc = K >> 6;

    prefetch_stage(op, sb, 0, bm, bn, lda, K, tid);
    if (nc > 1) prefetch_stage(op, sb, 1, bm, bn, lda, K, tid);

    for (int c = 0; c < nc; c++) {
        if (c + 2 < nc) {
            prefetch_stage(op, sb, c + 2, bm, bn, lda, K, tid);
            asm volatile("cp.async.wait_group 2;");
        } else if (c + 1 < nc) {
            asm volatile("cp.async.wait_group 1;");
        } else {
            asm volatile("cp.async.wait_group 0;");
        }
        __syncthreads();

        const int st = c % 3;
        const uint32_t abase = sb + st * STAGE_B;
        const uint32_t wbase = abase + 16384;

#pragma unroll
        for (int kk = 0; kk < 4; kk++) {   // K=16 steps within BK=64
            uint32_t a[4][4], b[2][4];
#pragma unroll
            for (int mf = 0; mf < 4; mf++) {
                int r   = wm + mf * 16 + ((lane >> 3) & 1) * 8 + (lane & 7);
                int cch = kk * 2 + (lane >> 4);
                ldsm4(a[mf], abase + r * 128 + ((cch ^ (r & 7)) << 4));
            }
#pragma unroll
            for (int nf = 0; nf < 2; nf++) {
                int r   = wn + nf * 16 + ((lane >> 4) & 1) * 8 + (lane & 7);
                int cch = kk * 2 + ((lane >> 3) & 1);
                ldsm4(b[nf], wbase + r * 128 + ((cch ^ (r & 7)) << 4));
            }
#pragma unroll
            for (int mf = 0; mf < 4; mf++)
#pragma unroll
                for (int nt = 0; nt < 4; nt++)
                    mma16816(acc[mf][nt], a[mf],
                             b[nt >> 1][(nt & 1) * 2], b[nt >> 1][(nt & 1) * 2 + 1]);
        }
        __syncthreads();
    }

    // epilogue: bias + fp32 store
#pragma unroll
    for (int mf = 0; mf < 4; mf++) {
        int row = bm + wm + mf * 16 + (lane >> 2);
#pragma unroll
        for (int nt = 0; nt < 4; nt++) {
            int col = bn + wn + nt * 8 + (lane & 3) * 2;
            float b0 = op.bias[col], b1 = op.bias[col + 1];
            float2 v0 = make_float2(acc[mf][nt][0] + b0, acc[mf][nt][1] + b1);
            float2 v1 = make_float2(acc[mf][nt][2] + b0, acc[mf][nt][3] + b1);
            *(float2*)(op.C + (size_t)row * ldc + col) = v0;
            *(float2*)(op.C + (size_t)(row + 8) * ldc + col) = v1;
        }
    }
}

// ============================================================================
// small kernels
// ============================================================================
__global__ void zero_f32(float* p, int n)
{
    int i = blockIdx.x * blockDim.x + threadIdx.x;
    if (i < n) p[i] = 0.f;
}
__global__ void zero_bf16(__nv_bfloat16* p, int n)
{
    int i = blockIdx.x * blockDim.x + threadIdx.x;
    if (i < n) p[i] = __float2bfloat16(0.f);
}

// fp32 [rows,K] -> stacked bf16 [rows, Kp*nseg]; per-seg mode: 0=hi, 1=lo, 2=zero
__global__ void convert_stack(const float* __restrict__ src, __nv_bfloat16* __restrict__ dst,
                              int K, int Kp, int nseg, int modes, int total)
{
    int i = blockIdx.x * blockDim.x + threadIdx.x;
    if (i >= total) return;
    int Kt  = Kp * nseg;
    int row = i / Kt;
    int rem = i - row * Kt;
    int seg = rem / Kp;
    int kk  = rem - seg * Kp;
    int mode = (modes >> (2 * seg)) & 3;
    float v = (mode != 2 && kk < K) ? src[(size_t)row * K + kk] : 0.f;
    __nv_bfloat16 h = __float2bfloat16(v);
    __nv_bfloat16 o = h;
    if (mode == 1) o = __float2bfloat16(v - __bfloat162float(h));
    dst[i] = o;
}

__device__ __forceinline__ float sigmoidf_(float x) { return 1.f / (1.f + expf(-x)); }
__device__ __forceinline__ void split_bf16(float v, __nv_bfloat16& h, __nv_bfloat16& l) {
    h = __float2bfloat16(v);
    l = __float2bfloat16(v - __bfloat162float(h));
}

// Layer-0 gating, both directions (blockIdx.y = dir). fp32 state + stacked writes.
__global__ void gru_gate_l0(int s)
{
    const int idx = blockIdx.x * blockDim.x + threadIdx.x;  // over B*H
    const int dir = blockIdx.y;
    const int b = idx >> 9;
    const int j = idx & 511;
    const int t = (dir == 0) ? s : (Tt - 1 - s);

    const float* gx  = (dir == 0 ? g_gxA : g_gxB) + ((size_t)b * Tt + t) * Gg;
    const float* ghp = g_gh + ((size_t)dir * Bv + b) * Gg;
    const size_t hidx = ((size_t)dir * Bv + b) * Hh + j;

    float r = sigmoidf_(gx[j] + ghp[j]);
    float z = sigmoidf_(gx[Hh + j] + ghp[Hh + j]);
    float n = tanhf(gx[2 * Hh + j] + r * ghp[2 * Hh + j]);
    float hn = (1.f - z) * n + z * g_h[hidx];
    g_h[hidx] = hn;

    __nv_bfloat16 hh, hl;
    split_bf16(hn, hh, hl);
    __nv_bfloat16* hs = g_hs + (size_t)dir * (Bv * Gg) + (size_t)b * Gg;
    hs[j] = hh; hs[Hh + j] = hh; hs[2 * Hh + j] = hl;

    const size_t yrow = ((size_t)b * Tt + t) * 3072;
    const int c = dir * Hh + j;
    g_y0s[yrow + c] = hh;
    g_y0s[yrow + 1024 + c] = hh;
    g_y0s[yrow + 2048 + c] = hl;
}

__global__ void gru_gate_l1(int s)
{
    const int idx = blockIdx.x * blockDim.x + threadIdx.x;
    const int b = idx >> 9;
    const int j = idx & 511;

    const float* gx  = g_gxA + ((size_t)b * Tt + s) * Gg;
    const float* ghp = g_gh + (size_t)b * Gg;
    const size_t hidx = (size_t)b * Hh + j;

    float r = sigmoidf_(gx[j] + ghp[j]);
    float z = sigmoidf_(gx[Hh + j] + ghp[Hh + j]);
    float n = tanhf(gx[2 * Hh + j] + r * ghp[2 * Hh + j]);
    float hn = (1.f - z) * n + z * g_h1[hidx];
    g_h1[hidx] = hn;

    __nv_bfloat16 hh, hl;
    split_bf16(hn, hh, hl);
    __nv_bfloat16* hs = g_h1s + (size_t)b * Gg;
    hs[j] = hh; hs[Hh + j] = hh; hs[2 * Hh + j] = hl;
}

// Layer-1 backward: output at original t=T-1 is the FIRST reversed step (h0=0).
__global__ void gate_l1b_last(const float* __restrict__ bhh)
{
    const int idx = blockIdx.x * blockDim.x + threadIdx.x;
    const int b = idx >> 9;
    const int j = idx & 511;
    const float* gx = g_gx1b + (size_t)b * Gg;
    float r = sigmoidf_(gx[j] + bhh[j]);
    float z = sigmoidf_(gx[Hh + j] + bhh[Hh + j]);
    float n = tanhf(gx[2 * Hh + j] + r * bhh[2 * Hh + j]);
    g_h1b[(size_t)b * Hh + j] = (1.f - z) * n;
}

__global__ void concat_last(void)
{
    const int idx = blockIdx.x * blockDim.x + threadIdx.x;  // B*2H
    const int b = idx >> 10;
    const int j = idx & 1023;
    float v = (j < Hh) ? g_h1[(size_t)b * Hh + j] : g_h1b[(size_t)b * Hh + (j - Hh)];
    __nv_bfloat16 hh, hl;
    split_bf16(v, hh, hl);
    __nv_bfloat16* ls = g_lasts + (size_t)b * 3072;
    ls[j] = hh; ls[1024 + j] = hh; ls[2048 + j] = hl;
}

// BN + ReLU + fc2 + log_softmax
__global__ void head_kernel(const float* __restrict__ gamma, const float* __restrict__ beta,
                            const float* __restrict__ mean, const float* __restrict__ var,
                            const float* __restrict__ fc2w, const float* __restrict__ fc2b,
                            float* __restrict__ out)
{
    const int b = blockIdx.x;
    const int tid = threadIdx.x;
    __shared__ float a[256];
    __shared__ float logits[10];

    float v = g_z1[(size_t)b * 256 + tid];
    v = (v - mean[tid]) * rsqrtf(var[tid] + 1e-5f) * gamma[tid] + beta[tid];
    a[tid] = fmaxf(v, 0.f);
    __syncthreads();

    if (tid < 10) {
        float acc = fc2b[tid];
        const float* wrow = fc2w + tid * 256;
        for (int k = 0; k < 256; k++) acc = fmaf(a[k], wrow[k], acc);
        logits[tid] = acc;
    }
    __syncthreads();

    if (tid == 0) {
        float mx = logits[0];
        for (int i = 1; i < 10; i++) mx = fmaxf(mx, logits[i]);
        float s = 0.f;
        for (int i = 0; i < 10; i++) s += expf(logits[i] - mx);
        float lse = mx + logf(s);
        for (int i = 0; i < 10; i++) out[(size_t)b * 10 + i] = logits[i] - lse;
    }
}

// ============================================================================
// host-side launch
// ============================================================================
extern "C" void kernel_launch(void* const* d_in, const int* in_sizes, int n_in,
                              void* d_out, int out_size)
{
    (void)in_sizes; (void)n_in; (void)out_size;
    const float* x         = (const float*)d_in[0];
    const float* W_ih_l0   = (const float*)d_in[1];
    const float* W_hh_l0   = (const float*)d_in[2];
    const float* b_ih_l0   = (const float*)d_in[3];
    const float* b_hh_l0   = (const float*)d_in[4];
    const float* W_ih_l0r  = (const float*)d_in[5];
    const float* W_hh_l0r  = (const float*)d_in[6];
    const float* b_ih_l0r  = (const float*)d_in[7];
    const float* b_hh_l0r  = (const float*)d_in[8];
    const float* W_ih_l1   = (const float*)d_in[9];
    const float* W_hh_l1   = (const float*)d_in[10];
    const float* b_ih_l1   = (const float*)d_in[11];
    const float* b_hh_l1   = (const float*)d_in[12];
    const float* W_ih_l1r  = (const float*)d_in[13];
    const float* W_hh_l1r  = (const float*)d_in[14];
    const float* b_ih_l1r  = (const float*)d_in[15];
    const float* b_hh_l1r  = (const float*)d_in[16];
    const float* fc1_w     = (const float*)d_in[17];
    const float* fc1_b     = (const float*)d_in[18];
    const float* bn_gamma  = (const float*)d_in[19];
    const float* bn_beta   = (const float*)d_in[20];
    const float* bn_mean   = (const float*)d_in[21];
    const float* bn_var    = (const float*)d_in[22];
    const float* fc2_w     = (const float*)d_in[23];
    const float* fc2_b     = (const float*)d_in[24];
    float* out = (float*)d_out;

    float *p_gxA, *p_gxB, *p_gh, *p_h, *p_h1, *p_gx1b, *p_z1;
    __nv_bfloat16 *p_xs, *p_ws, *p_y0s, *p_hs, *p_h1s, *p_ls;
    cudaGetSymbolAddress((void**)&p_gxA,  g_gxA);
    cudaGetSymbolAddress((void**)&p_gxB,  g_gxB);
    cudaGetSymbolAddress((void**)&p_gh,   g_gh);
    cudaGetSymbolAddress((void**)&p_h,    g_h);
    cudaGetSymbolAddress((void**)&p_h1,   g_h1);
    cudaGetSymbolAddress((void**)&p_gx1b, g_gx1b);
    cudaGetSymbolAddress((void**)&p_z1,   g_z1);
    cudaGetSymbolAddress((void**)&p_xs,   g_xs);
    cudaGetSymbolAddress((void**)&p_ws,   g_ws);
    cudaGetSymbolAddress((void**)&p_y0s,  g_y0s);
    cudaGetSymbolAddress((void**)&p_hs,   g_hs);
    cudaGetSymbolAddress((void**)&p_h1s,  g_h1s);
    cudaGetSymbolAddress((void**)&p_ls,   g_lasts);

    cudaFuncSetAttribute(mma_gemm, cudaFuncAttributeMaxDynamicSharedMemorySize, SMEM_SZ);

    const int BH = Bv * Hh;      // 2,097,152
    const int BG = Bv * Gg;      // 6,291,456
    const int MT = Bv * Tt;      // 114,688

    // seg-mode packs: 0=hi, 1=lo, 2=zero (2 bits per segment)
    const int MODES_A4 = 0 | (0 << 2) | (1 << 4) | (2 << 6);  // [hi|hi|lo|0]
    const int MODES_W4 = 0 | (1 << 2) | (0 << 4) | (2 << 6);  // [hi|lo|hi|0]
    const int MODES_W3 = 0 | (1 << 2) | (0 << 4);             // [hi|lo|hi]

    // 0) stack inputs/weights
    {
        int tot = MT * 128;
        convert_stack<<<(tot + 255) / 256, 256>>>(x, p_xs, In, 32, 4, MODES_A4, tot);
        struct { const float* s; int off, K, Kp, nseg, modes, rows; } cv[8] = {
            { W_ih_l0,  WS_IH_L0,  28,   32,   4, MODES_W4, 1536 },
            { W_ih_l0r, WS_IH_L0R, 28,   32,   4, MODES_W4, 1536 },
            { W_hh_l0,  WS_HH_L0,  512,  512,  3, MODES_W3, 1536 },
            { W_hh_l0r, WS_HH_L0R, 512,  512,  3, MODES_W3, 1536 },
            { W_hh_l1,  WS_HH_L1,  512,  512,  3, MODES_W3, 1536 },
            { W_ih_l1,  WS_IH_L1,  1024, 1024, 3, MODES_W3, 1536 },
            { W_ih_l1r, WS_IH_L1R, 1024, 1024, 3, MODES_W3, 1536 },
            { fc1_w,    WS_FC1,    1024, 1024, 3, MODES_W3, 256  },
        };
        for (int i = 0; i < 8; i++) {
            int t = cv[i].rows * cv[i].Kp * cv[i].nseg;
            convert_stack<<<(t + 255) / 256, 256>>>(cv[i].s, p_ws + cv[i].off,
                                                    cv[i].K, cv[i].Kp, cv[i].nseg,
                                                    cv[i].modes, t);
        }
    }

    // 1) zero states (fp32 + stacked mirrors)
    zero_f32<<<(2 * BH + 255) / 256, 256>>>(p_h, 2 * BH);
    zero_f32<<<(BH + 255) / 256, 256>>>(p_h1, BH);
    zero_bf16<<<(2 * BG + 255) / 256, 256>>>(p_hs, 2 * BG);
    zero_bf16<<<(BG + 255) / 256, 256>>>(p_h1s, BG);

    // 2) layer-0 input projections (fwd+bwd), K'=128
    {
        MOp f{ p_xs, p_ws + WS_IH_L0,  b_ih_l0,  p_gxA };
        MOp r{ p_xs, p_ws + WS_IH_L0R, b_ih_l0r, p_gxB };
        mma_gemm<<<dim3(Gg / 128, MT / 128, 2), 256, SMEM_SZ>>>(f, r, 128, Gg, 128);
    }

    // 3) layer-0 recurrence, K'=1536
    for (int s = 0; s < Tt; s++) {
        MOp f{ p_hs,      p_ws + WS_HH_L0,  b_hh_l0,  p_gh };
        MOp r{ p_hs + BG, p_ws + WS_HH_L0R, b_hh_l0r, p_gh + BG };
        mma_gemm<<<dim3(Gg / 128, Bv / 128, 2), 256, SMEM_SZ>>>(f, r, Gg, Gg, Gg);
        gru_gate_l0<<<dim3(BH / 256, 2), 256>>>(s);
    }

    // 4) layer-1 input projection (fwd, all t), K'=3072 — reuses g_gxA
    {
        MOp f{ p_y0s, p_ws + WS_IH_L1, b_ih_l1, p_gxA };
        mma_gemm<<<dim3(Gg / 128, MT / 128, 1), 256, SMEM_SZ>>>(f, f, 3072, Gg, 3072);
    }

    // 5) layer-1 bwd input projection at t=T-1 only
    {
        MOp f{ p_y0s + (size_t)(Tt - 1) * 3072, p_ws + WS_IH_L1R, b_ih_l1r, p_gx1b };
        mma_gemm<<<dim3(Gg / 128, Bv / 128, 1), 256, SMEM_SZ>>>(f, f, Tt * 3072, Gg, 3072);
    }
    gate_l1b_last<<<BH / 256, 256>>>(b_hh_l1r);

    // 6) layer-1 fwd recurrence, K'=1536
    for (int s = 0; s < Tt; s++) {
        MOp f{ p_h1s, p_ws + WS_HH_L1, b_hh_l1, p_gh };
        mma_gemm<<<dim3(Gg / 128, Bv / 128, 1), 256, SMEM_SZ>>>(f, f, Gg, Gg, Gg);
        gru_gate_l1<<<BH / 256, 256>>>(s);
    }

    // 7) head
    concat_last<<<(Bv * H2) / 256, 256>>>();
    {
        MOp f{ p_ls, p_ws + WS_FC1, fc1_b, p_z1 };
        mma_gemm<<<dim3(256 / 128, Bv / 128, 1), 256, SMEM_SZ>>>(f, f, 3072, 256, 3072);
    }
    head_kernel<<<Bv, 256>>>(bn_gamma, bn_beta, bn_mean, bn_var, fc2_w, fc2_b, out);
}